// round 1
// baseline (speedup 1.0000x reference)
#include <cuda_runtime.h>
#include <math.h>

// Scratch (no device allocations allowed)
__device__ float g_s[32 * 512];     // channel means
__device__ float g_gate[32 * 512];  // sigmoid gate

#define BATCH 32
#define CIN 512
#define HID 64
#define PLANE 4096           // 64*64
#define NKNOT 12             // GRID_SIZE + 2*SPLINE_ORDER + 1 = 12
#define NBASE 8              // GRID_SIZE + SPLINE_ORDER

__device__ __forceinline__ float siluf(float v) {
    return v / (1.0f + __expf(-v));
}

// Cox-de Boor, exactly mirroring the reference recursion.
// t: 12 knots, out: 8 basis values of order 3 at x.
__device__ __forceinline__ void bspline8(float x, const float* t, float* out) {
    float b[11];
#pragma unroll
    for (int j = 0; j < 11; j++)
        b[j] = (x >= t[j] && x < t[j + 1]) ? 1.0f : 0.0f;
#pragma unroll
    for (int k = 1; k <= 3; k++) {
#pragma unroll
        for (int j = 0; j < 10; j++) {
            if (j <= 10 - k) {
                float left  = (x - t[j]) / (t[j + k] - t[j]) * b[j];
                float right = (t[j + k + 1] - x) / (t[j + k + 1] - t[j + 1]) * b[j + 1];
                b[j] = left + right;
            }
        }
    }
#pragma unroll
    for (int j = 0; j < NBASE; j++) out[j] = b[j];
}

// ---------------------------------------------------------------------------
// Kernel 1: per-(b,c) plane mean. One block per plane, 256 threads, float4.
// ---------------------------------------------------------------------------
__global__ void __launch_bounds__(256) mean_kernel(const float4* __restrict__ x,
                                                   float* __restrict__ s_out) {
    const int plane = blockIdx.x;
    const float4* p = x + (size_t)plane * (PLANE / 4);
    float sum = 0.0f;
#pragma unroll
    for (int it = 0; it < 4; it++) {
        float4 v = p[it * 256 + threadIdx.x];
        sum += (v.x + v.y) + (v.z + v.w);
    }
#pragma unroll
    for (int off = 16; off >= 1; off >>= 1)
        sum += __shfl_xor_sync(0xffffffffu, sum, off);

    __shared__ float ws[8];
    if ((threadIdx.x & 31) == 0) ws[threadIdx.x >> 5] = sum;
    __syncthreads();
    if (threadIdx.x == 0) {
        float tot = 0.0f;
#pragma unroll
        for (int w = 0; w < 8; w++) tot += ws[w];
        float m = tot * (1.0f / (float)PLANE);
        // nan_to_num
        if (isnan(m)) m = 0.0f;
        m = fminf(fmaxf(m, -3.402823466e38f), 3.402823466e38f);
        s_out[plane] = m;
    }
}

// ---------------------------------------------------------------------------
// Kernel 2: KAN forward for all 32 batch rows. One block per batch, 512 thr.
// ---------------------------------------------------------------------------
__global__ void __launch_bounds__(512) kan_gate_kernel(
    const float* __restrict__ s_in,
    const float* __restrict__ grid1, const float* __restrict__ bw1,
    const float* __restrict__ sw1,  const float* __restrict__ sc1,
    const float* __restrict__ grid2, const float* __restrict__ bw2,
    const float* __restrict__ sw2,  const float* __restrict__ sc2,
    float* __restrict__ gate) {

    __shared__ float sh_silu[CIN];
    __shared__ float sh_b[CIN][NBASE];
    __shared__ float sh_h2[HID];         // silu(silu(layer1 out)) for base path
    __shared__ float sh_b2[HID][NBASE];  // bases of silu(layer1 out)

    const int b = blockIdx.x;
    const int tid = threadIdx.x;

    // ---- layer 1 input prep: silu(s) and bases(s) per input feature ----
    {
        float s = s_in[b * CIN + tid];
        sh_silu[tid] = siluf(s);
        float t[NKNOT];
#pragma unroll
        for (int j = 0; j < NKNOT; j++) t[j] = grid1[tid * NKNOT + j];
        float bb[NBASE];
        bspline8(s, t, bb);
#pragma unroll
        for (int k = 0; k < NBASE; k++) sh_b[tid][k] = bb[k];
    }
    __syncthreads();

    // ---- layer 1: 64 outputs, 8 threads each ----
    {
        const int o = tid >> 3;       // 0..63
        const int l = tid & 7;        // lane within group
        const float* bwrow = bw1 + o * CIN;
        const float* scrow = sc1 + o * CIN;
        const float* swrow = sw1 + (size_t)o * CIN * NBASE;
        float acc = 0.0f;
        for (int i = l; i < CIN; i += 8) {
            acc += sh_silu[i] * bwrow[i];
            float sp = 0.0f;
#pragma unroll
            for (int k = 0; k < NBASE; k++)
                sp += sh_b[i][k] * swrow[i * NBASE + k];
            acc += sp * scrow[i];
        }
#pragma unroll
        for (int off = 4; off >= 1; off >>= 1)
            acc += __shfl_xor_sync(0xffffffffu, acc, off);

        if (l == 0) {
            float h = siluf(acc);       // silu between the two KAN layers
            sh_h2[o] = siluf(h);        // base path of layer 2 applies silu again
            float t2[NKNOT];
#pragma unroll
            for (int j = 0; j < NKNOT; j++) t2[j] = grid2[o * NKNOT + j];
            float bb2[NBASE];
            bspline8(h, t2, bb2);
#pragma unroll
            for (int k = 0; k < NBASE; k++) sh_b2[o][k] = bb2[k];
        }
    }
    __syncthreads();

    // ---- layer 2: one output channel per thread ----
    {
        const float* bwrow = bw2 + tid * HID;
        const float* scrow = sc2 + tid * HID;
        const float* swrow = sw2 + (size_t)tid * HID * NBASE;
        float acc = 0.0f;
#pragma unroll 4
        for (int o = 0; o < HID; o++) {
            acc += sh_h2[o] * bwrow[o];
            float sp = 0.0f;
#pragma unroll
            for (int k = 0; k < NBASE; k++)
                sp += sh_b2[o][k] * swrow[o * NBASE + k];
            acc += sp * scrow[o];
        }
        gate[b * CIN + tid] = 1.0f / (1.0f + __expf(-acc));
    }
}

// ---------------------------------------------------------------------------
// Kernel 3: out = x * gate (broadcast per plane). One block per plane.
// ---------------------------------------------------------------------------
__global__ void __launch_bounds__(256) apply_kernel(const float4* __restrict__ x,
                                                    const float* __restrict__ gate,
                                                    float4* __restrict__ out) {
    const int plane = blockIdx.x;
    const float g = gate[plane];
    const float4* p = x + (size_t)plane * (PLANE / 4);
    float4* q = out + (size_t)plane * (PLANE / 4);
#pragma unroll
    for (int it = 0; it < 4; it++) {
        int i = it * 256 + threadIdx.x;
        float4 v = p[i];
        v.x *= g; v.y *= g; v.z *= g; v.w *= g;
        q[i] = v;
    }
}

extern "C" void kernel_launch(void* const* d_in, const int* in_sizes, int n_in,
                              void* d_out, int out_size) {
    const float* x     = (const float*)d_in[0];
    const float* grid1 = (const float*)d_in[1];
    const float* bw1   = (const float*)d_in[2];
    const float* sw1   = (const float*)d_in[3];
    const float* sc1   = (const float*)d_in[4];
    const float* grid2 = (const float*)d_in[5];
    const float* bw2   = (const float*)d_in[6];
    const float* sw2   = (const float*)d_in[7];
    const float* sc2   = (const float*)d_in[8];
    float* out = (float*)d_out;

    float* s_buf;
    float* gate_buf;
    cudaGetSymbolAddress((void**)&s_buf, g_s);
    cudaGetSymbolAddress((void**)&gate_buf, g_gate);

    const int nplanes = BATCH * CIN;  // 16384

    mean_kernel<<<nplanes, 256>>>((const float4*)x, s_buf);
    kan_gate_kernel<<<BATCH, 512>>>(s_buf, grid1, bw1, sw1, sc1,
                                    grid2, bw2, sw2, sc2, gate_buf);
    apply_kernel<<<nplanes, 256>>>((const float4*)x, gate_buf, (float4*)out);
}

// round 2
// speedup vs baseline: 1.9942x; 1.9942x over previous
#include <cuda_runtime.h>
#include <math.h>

// Scratch (no device allocations allowed)
__device__ float g_silu[32 * 512];          // silu(mean) per (b,c)
__device__ float g_bases[32 * 512 * 8];     // layer-1 spline bases
__device__ float g_h2silu[32 * 64];         // silu(silu(layer1 out))
__device__ float g_bases2[32 * 64 * 8];     // layer-2 spline bases
__device__ float g_gate[32 * 512];          // sigmoid gate

#define BATCH 32
#define CIN 512
#define HID 64
#define PLANE 4096           // 64*64
#define NKNOT 12             // GRID_SIZE + 2*SPLINE_ORDER + 1
#define NBASE 8              // GRID_SIZE + SPLINE_ORDER

__device__ __forceinline__ float siluf(float v) {
    return v / (1.0f + __expf(-v));
}

// Cox-de Boor, mirroring the reference recursion. t: 12 knots -> 8 order-3 bases.
__device__ __forceinline__ void bspline8(float x, const float* t, float* out) {
    float b[11];
#pragma unroll
    for (int j = 0; j < 11; j++)
        b[j] = (x >= t[j] && x < t[j + 1]) ? 1.0f : 0.0f;
#pragma unroll
    for (int k = 1; k <= 3; k++) {
#pragma unroll
        for (int j = 0; j < 10; j++) {
            if (j <= 10 - k) {
                float left  = (x - t[j]) / (t[j + k] - t[j]) * b[j];
                float right = (t[j + k + 1] - x) / (t[j + k + 1] - t[j + 1]) * b[j + 1];
                b[j] = left + right;
            }
        }
    }
#pragma unroll
    for (int j = 0; j < NBASE; j++) out[j] = b[j];
}

// ---------------------------------------------------------------------------
// Kernel 1: per-(b,c) plane mean + fused silu/bases prep. One block per plane.
// ---------------------------------------------------------------------------
__global__ void __launch_bounds__(256) mean_prep_kernel(
    const float4* __restrict__ x,
    const float* __restrict__ grid1,
    float* __restrict__ silu_out,
    float* __restrict__ bases_out) {
    const int plane = blockIdx.x;
    const float4* p = x + (size_t)plane * (PLANE / 4);
    float sum = 0.0f;
#pragma unroll
    for (int it = 0; it < 4; it++) {
        float4 v = p[it * 256 + threadIdx.x];
        sum += (v.x + v.y) + (v.z + v.w);
    }
#pragma unroll
    for (int off = 16; off >= 1; off >>= 1)
        sum += __shfl_xor_sync(0xffffffffu, sum, off);

    __shared__ float ws[8];
    if ((threadIdx.x & 31) == 0) ws[threadIdx.x >> 5] = sum;
    __syncthreads();
    if (threadIdx.x == 0) {
        float tot = 0.0f;
#pragma unroll
        for (int w = 0; w < 8; w++) tot += ws[w];
        float m = tot * (1.0f / (float)PLANE);
        if (isnan(m)) m = 0.0f;
        m = fminf(fmaxf(m, -3.402823466e38f), 3.402823466e38f);

        const int c = plane & (CIN - 1);
        float t[NKNOT];
#pragma unroll
        for (int j = 0; j < NKNOT; j++) t[j] = grid1[c * NKNOT + j];
        float bb[NBASE];
        bspline8(m, t, bb);
#pragma unroll
        for (int k = 0; k < NBASE; k++) bases_out[plane * NBASE + k] = bb[k];
        silu_out[plane] = siluf(m);
    }
}

// ---------------------------------------------------------------------------
// Kernel 2: KAN layer 1. One block per (o, b): 64 x 32 = 2048 blocks, 128 thr.
// Also emits the layer-2 input's silu + bases (depends only on this output).
// ---------------------------------------------------------------------------
__global__ void __launch_bounds__(128) kan1_kernel(
    const float* __restrict__ silu_in,      // [32,512]
    const float* __restrict__ bases_in,     // [32,512,8]
    const float* __restrict__ bw1,          // [64,512]
    const float* __restrict__ sw1,          // [64,512,8]
    const float* __restrict__ sc1,          // [64,512]
    const float* __restrict__ grid2,        // [64,12]
    float* __restrict__ h2silu_out,         // [32,64]
    float* __restrict__ bases2_out) {       // [32,64,8]
    const int o = blockIdx.x;   // 0..63
    const int b = blockIdx.y;   // 0..31
    const int tid = threadIdx.x;

    const float4* bases4 = (const float4*)(bases_in + (size_t)b * CIN * NBASE);
    const float4* sw4    = (const float4*)(sw1 + (size_t)o * CIN * NBASE);
    const float*  sl     = silu_in + b * CIN;
    const float*  bwrow  = bw1 + o * CIN;
    const float*  scrow  = sc1 + o * CIN;

    float acc = 0.0f;
#pragma unroll
    for (int it = 0; it < 4; it++) {
        int i = it * 128 + tid;
        float4 ba = bases4[i * 2];
        float4 bb = bases4[i * 2 + 1];
        float4 wa = sw4[i * 2];
        float4 wb = sw4[i * 2 + 1];
        float sp = ba.x * wa.x + ba.y * wa.y + ba.z * wa.z + ba.w * wa.w
                 + bb.x * wb.x + bb.y * wb.y + bb.z * wb.z + bb.w * wb.w;
        acc += sl[i] * bwrow[i] + sp * scrow[i];
    }
#pragma unroll
    for (int off = 16; off >= 1; off >>= 1)
        acc += __shfl_xor_sync(0xffffffffu, acc, off);

    __shared__ float ws[4];
    if ((tid & 31) == 0) ws[tid >> 5] = acc;
    __syncthreads();
    if (tid == 0) {
        float y1 = ws[0] + ws[1] + ws[2] + ws[3];
        float h = siluf(y1);                 // input to layer 2
        h2silu_out[b * HID + o] = siluf(h);  // layer-2 base path
        float t[NKNOT];
#pragma unroll
        for (int j = 0; j < NKNOT; j++) t[j] = grid2[o * NKNOT + j];
        float bb2[NBASE];
        bspline8(h, t, bb2);
#pragma unroll
        for (int k = 0; k < NBASE; k++)
            bases2_out[(b * HID + o) * NBASE + k] = bb2[k];
    }
}

// ---------------------------------------------------------------------------
// Kernel 3: KAN layer 2 + sigmoid. One block per (c, b): 512 x 32, 64 threads.
// ---------------------------------------------------------------------------
__global__ void __launch_bounds__(64) kan2_kernel(
    const float* __restrict__ h2silu,       // [32,64]
    const float* __restrict__ bases2,       // [32,64,8]
    const float* __restrict__ bw2,          // [512,64]
    const float* __restrict__ sw2,          // [512,64,8]
    const float* __restrict__ sc2,          // [512,64]
    float* __restrict__ gate) {             // [32,512]
    const int c = blockIdx.x;   // 0..511
    const int b = blockIdx.y;   // 0..31
    const int j = threadIdx.x;  // 0..63

    const float4* bases4 = (const float4*)(bases2 + (size_t)b * HID * NBASE);
    const float4* sw4    = (const float4*)(sw2 + (size_t)c * HID * NBASE);

    float4 ba = bases4[j * 2];
    float4 bb = bases4[j * 2 + 1];
    float4 wa = sw4[j * 2];
    float4 wb = sw4[j * 2 + 1];
    float sp = ba.x * wa.x + ba.y * wa.y + ba.z * wa.z + ba.w * wa.w
             + bb.x * wb.x + bb.y * wb.y + bb.z * wb.z + bb.w * wb.w;
    float acc = h2silu[b * HID + j] * bw2[c * HID + j] + sp * sc2[c * HID + j];

#pragma unroll
    for (int off = 16; off >= 1; off >>= 1)
        acc += __shfl_xor_sync(0xffffffffu, acc, off);

    __shared__ float ws[2];
    if ((j & 31) == 0) ws[j >> 5] = acc;
    __syncthreads();
    if (j == 0) {
        float y = ws[0] + ws[1];
        gate[b * CIN + c] = 1.0f / (1.0f + __expf(-y));
    }
}

// ---------------------------------------------------------------------------
// Kernel 4: out = x * gate (broadcast per plane). One block per plane.
// ---------------------------------------------------------------------------
__global__ void __launch_bounds__(256) apply_kernel(const float4* __restrict__ x,
                                                    const float* __restrict__ gate,
                                                    float4* __restrict__ out) {
    const int plane = blockIdx.x;
    const float g = gate[plane];
    const float4* p = x + (size_t)plane * (PLANE / 4);
    float4* q = out + (size_t)plane * (PLANE / 4);
#pragma unroll
    for (int it = 0; it < 4; it++) {
        int i = it * 256 + threadIdx.x;
        float4 v = p[i];
        v.x *= g; v.y *= g; v.z *= g; v.w *= g;
        q[i] = v;
    }
}

extern "C" void kernel_launch(void* const* d_in, const int* in_sizes, int n_in,
                              void* d_out, int out_size) {
    const float* x     = (const float*)d_in[0];
    const float* grid1 = (const float*)d_in[1];
    const float* bw1   = (const float*)d_in[2];
    const float* sw1   = (const float*)d_in[3];
    const float* sc1   = (const float*)d_in[4];
    const float* grid2 = (const float*)d_in[5];
    const float* bw2   = (const float*)d_in[6];
    const float* sw2   = (const float*)d_in[7];
    const float* sc2   = (const float*)d_in[8];
    float* out = (float*)d_out;

    float *silu_buf, *bases_buf, *h2silu_buf, *bases2_buf, *gate_buf;
    cudaGetSymbolAddress((void**)&silu_buf,   g_silu);
    cudaGetSymbolAddress((void**)&bases_buf,  g_bases);
    cudaGetSymbolAddress((void**)&h2silu_buf, g_h2silu);
    cudaGetSymbolAddress((void**)&bases2_buf, g_bases2);
    cudaGetSymbolAddress((void**)&gate_buf,   g_gate);

    const int nplanes = BATCH * CIN;  // 16384

    mean_prep_kernel<<<nplanes, 256>>>((const float4*)x, grid1, silu_buf, bases_buf);
    kan1_kernel<<<dim3(HID, BATCH), 128>>>(silu_buf, bases_buf, bw1, sw1, sc1,
                                           grid2, h2silu_buf, bases2_buf);
    kan2_kernel<<<dim3(CIN, BATCH), 64>>>(h2silu_buf, bases2_buf, bw2, sw2, sc2,
                                          gate_buf);
    apply_kernel<<<nplanes, 256>>>((const float4*)x, gate_buf, (float4*)out);
}